// round 3
// baseline (speedup 1.0000x reference)
#include <cuda_runtime.h>

// Problem constants
#define NB 4096
#define NT 512
#define NC 4
#define NH 32
#define NO 3

// Tiling
#define ROWS 4                 // batch rows per block (1 per half-warp)
#define NTHREADS 64            // 2 warps
#define TCHUNK 16
#define NCHUNK (NT / TCHUNK)   // 32

// Shared: seq staging only (h never touches smem now)
#define SROW 68                // 16 t x 4 floats + 4 pad

__device__ __forceinline__ unsigned long long pk2(float lo, float hi) {
    unsigned long long d;
    asm("mov.b64 %0, {%1, %2};" : "=l"(d) : "f"(lo), "f"(hi));
    return d;
}
__device__ __forceinline__ void upk2(unsigned long long v, float& lo, float& hi) {
    asm("mov.b64 {%0, %1}, %2;" : "=f"(lo), "=f"(hi) : "l"(v));
}
// Packed dual-FMA (FFMA2 in SASS): 2 MACs per issue.
__device__ __forceinline__ unsigned long long fma2(unsigned long long a,
                                                   unsigned long long b,
                                                   unsigned long long c) {
    unsigned long long d;
    asm("fma.rn.f32x2 %0, %1, %2, %3;" : "=l"(d) : "l"(a), "l"(b), "l"(c));
    return d;
}
__device__ __forceinline__ unsigned long long add2(unsigned long long a,
                                                   unsigned long long b) {
    unsigned long long d;
    asm("add.rn.f32x2 %0, %1, %2;" : "=l"(d) : "l"(a), "l"(b));
    return d;
}
__device__ __forceinline__ void lds_2x64(unsigned addr, unsigned long long& a,
                                         unsigned long long& b) {
    asm volatile("ld.shared.v2.u64 {%0, %1}, [%2];" : "=l"(a), "=l"(b) : "r"(addr));
}
__device__ __forceinline__ void sts_v4(unsigned addr, float a, float b, float c, float d) {
    asm volatile("st.shared.v4.b32 [%0], {%1, %2, %3, %4};"
                 :: "r"(addr), "f"(a), "f"(b), "f"(c), "f"(d) : "memory");
}

__global__ void __launch_bounds__(NTHREADS, 7)
rnn_fused_kernel(const float* __restrict__ seq,
                 const float* __restrict__ w_ih,
                 const float* __restrict__ w_hh,
                 const float* __restrict__ b_ih,
                 const float* __restrict__ b_hh,
                 const float* __restrict__ fc_w,
                 const float* __restrict__ fc_b,
                 float* __restrict__ out) {
    __shared__ float ss[ROWS * SROW];    // seq chunk staging

    const int tid   = threadIdx.x;
    const int lane  = tid & 31;
    const int warp  = tid >> 5;
    const int half  = lane >> 4;
    const int g     = lane & 15;         // lane within half-warp: owns hidden 2g, 2g+1
    const int row_l = warp * 2 + half;   // row within block
    const int row   = blockIdx.x * ROWS + row_l;
    const int j0 = 2 * g, j1 = 2 * g + 1;

    // ---- one-time weight load, k-packed pairs (k=2p, 2p+1) ----
    unsigned long long wA[NH / 2], wB[NH / 2];
#pragma unroll
    for (int p = 0; p < NH / 2; p++) {
        wA[p] = pk2(w_hh[j0 * NH + 2 * p], w_hh[j0 * NH + 2 * p + 1]);
        wB[p] = pk2(w_hh[j1 * NH + 2 * p], w_hh[j1 * NH + 2 * p + 1]);
    }
    const unsigned long long wiA0 = pk2(w_ih[j0 * NC + 0], w_ih[j0 * NC + 1]);
    const unsigned long long wiA1 = pk2(w_ih[j0 * NC + 2], w_ih[j0 * NC + 3]);
    const unsigned long long wiB0 = pk2(w_ih[j1 * NC + 0], w_ih[j1 * NC + 1]);
    const unsigned long long wiB1 = pk2(w_ih[j1 * NC + 2], w_ih[j1 * NC + 3]);

    // bias folded as (bias, 0): the end-of-step horizontal add counts it once
    const unsigned long long biasA = pk2(b_ih[j0] + b_hh[j0], 0.0f);
    const unsigned long long biasB = pk2(b_ih[j1] + b_hh[j1], 0.0f);

    const unsigned sbase = (unsigned)__cvta_generic_to_shared(ss);
    const unsigned srow  = sbase + row_l * (SROW * 4);

    const float* seqp = seq + (size_t)row * (NT * NC);

    // prefetch seq chunk 0 (lane g -> timestep g of chunk)
    float4 nxt = *(const float4*)(seqp + g * NC);

    // h(t=0) = 0, fully register-resident pair
    unsigned long long hpair = 0ULL;

    for (int ch = 0; ch < NCHUNK; ch++) {
        // stage seq chunk: 16 B per timestep per row
        sts_v4(srow + g * 16, nxt.x, nxt.y, nxt.z, nxt.w);
        __syncwarp();                      // only sync left: once per 16 steps
        if (ch + 1 < NCHUNK)
            nxt = *(const float4*)(seqp + ((ch + 1) * TCHUNK + g) * NC);

#pragma unroll
        for (int tt = 0; tt < TCHUNK; tt++) {
            // x_proj seeds (off the h critical chain)
            unsigned long long sa, sb;
            lds_2x64(srow + tt * 16, sa, sb);
            unsigned long long accA0 = fma2(sa, wiA0, biasA);
            unsigned long long accB0 = fma2(sa, wiB0, biasB);
            unsigned long long accA1 = fma2(sb, wiA1, 0ULL);
            unsigned long long accB1 = fma2(sb, wiB1, 0ULL);

            // recurrence: gather the 16 h-pairs via width-16 shuffles.
            // One SHFL instruction serves both half-warps (both rows) at once.
#pragma unroll
            for (int p = 0; p < NH / 2; p++) {
                const unsigned long long hp =
                    __shfl_sync(0xffffffffu, hpair, p, 16);
                if (p & 1) {
                    accA1 = fma2(wA[p], hp, accA1);
                    accB1 = fma2(wB[p], hp, accB1);
                } else {
                    accA0 = fma2(wA[p], hp, accA0);
                    accB0 = fma2(wB[p], hp, accB0);
                }
            }

            // horizontal reduce + relu, repack new h pair (registers only)
            float aLo, aHi, bLo, bHi;
            upk2(add2(accA0, accA1), aLo, aHi);
            upk2(add2(accB0, accB1), bLo, bHi);
            const float a = fmaxf(aLo + aHi, 0.0f);
            const float b = fmaxf(bLo + bHi, 0.0f);
            hpair = pk2(a, b);
        }
    }

    // ---- FC head via shuffle reduction (h never left registers) ----
    float hLo, hHi;
    upk2(hpair, hLo, hHi);
    float p0 = fmaf(hLo, fc_w[0 * NH + j0], hHi * fc_w[0 * NH + j1]);
    float p1 = fmaf(hLo, fc_w[1 * NH + j0], hHi * fc_w[1 * NH + j1]);
    float p2 = fmaf(hLo, fc_w[2 * NH + j0], hHi * fc_w[2 * NH + j1]);
#pragma unroll
    for (int off = 8; off >= 1; off >>= 1) {
        p0 += __shfl_xor_sync(0xffffffffu, p0, off, 16);
        p1 += __shfl_xor_sync(0xffffffffu, p1, off, 16);
        p2 += __shfl_xor_sync(0xffffffffu, p2, off, 16);
    }
    if (g == 0) {
        out[row * NO + 0] = p0 + fc_b[0];
        out[row * NO + 1] = p1 + fc_b[1];
        out[row * NO + 2] = p2 + fc_b[2];
    }
}

extern "C" void kernel_launch(void* const* d_in, const int* in_sizes, int n_in,
                              void* d_out, int out_size) {
    const float* seq  = (const float*)d_in[0];
    const float* w_ih = (const float*)d_in[1];
    const float* w_hh = (const float*)d_in[2];
    const float* b_ih = (const float*)d_in[3];
    const float* b_hh = (const float*)d_in[4];
    const float* fc_w = (const float*)d_in[5];
    const float* fc_b = (const float*)d_in[6];
    float* out = (float*)d_out;

    rnn_fused_kernel<<<NB / ROWS, NTHREADS>>>(seq, w_ih, w_hh, b_ih, b_hh,
                                              fc_w, fc_b, out);
}

// round 4
// speedup vs baseline: 1.2405x; 1.2405x over previous
#include <cuda_runtime.h>

// Problem constants
#define NB 4096
#define NT 512
#define NC 4
#define NH 32
#define NO 3

// Layout: 32-thread blocks (1 warp). Warp handles 4 batch rows,
// 8 lanes per row, each lane owns h[4q .. 4q+3] in two packed f32x2 regs.
#define ROWS_PER_WARP 4
#define NBLOCKS (NB / ROWS_PER_WARP)   // 1024

__device__ __forceinline__ unsigned long long pk2(float lo, float hi) {
    unsigned long long d;
    asm("mov.b64 %0, {%1, %2};" : "=l"(d) : "f"(lo), "f"(hi));
    return d;
}
__device__ __forceinline__ void upk2(unsigned long long v, float& lo, float& hi) {
    asm("mov.b64 {%0, %1}, %2;" : "=f"(lo), "=f"(hi) : "l"(v));
}
// Packed dual-FMA (FFMA2 in SASS): 2 MACs per issue.
__device__ __forceinline__ unsigned long long fma2(unsigned long long a,
                                                   unsigned long long b,
                                                   unsigned long long c) {
    unsigned long long d;
    asm("fma.rn.f32x2 %0, %1, %2, %3;" : "=l"(d) : "l"(a), "l"(b), "l"(c));
    return d;
}
__device__ __forceinline__ unsigned long long add2(unsigned long long a,
                                                   unsigned long long b) {
    unsigned long long d;
    asm("add.rn.f32x2 %0, %1, %2;" : "=l"(d) : "l"(a), "l"(b));
    return d;
}

__global__ void __launch_bounds__(32)
rnn_fused_kernel(const float* __restrict__ seq,
                 const float* __restrict__ w_ih,
                 const float* __restrict__ w_hh,
                 const float* __restrict__ b_ih,
                 const float* __restrict__ b_hh,
                 const float* __restrict__ fc_w,
                 const float* __restrict__ fc_b,
                 float* __restrict__ out) {
    const int lane = threadIdx.x;        // 0..31
    const int q    = lane & 7;           // lane within row group
    const int r    = lane >> 3;          // row within warp (0..3)
    const int row  = blockIdx.x * ROWS_PER_WARP + r;
    const int jb   = 4 * q;              // first owned hidden index

    // ---- one-time weights into registers ----
    // w_hh rows jb..jb+3, k-packed into f32x2 pairs (float2 loads = pre-packed)
    unsigned long long w2[4][NH / 2];
#pragma unroll
    for (int jj = 0; jj < 4; jj++) {
        const float2* wp = (const float2*)(w_hh + (jb + jj) * NH);
#pragma unroll
        for (int p = 0; p < NH / 2; p++) {
            const float2 f = wp[p];
            w2[jj][p] = pk2(f.x, f.y);
        }
    }
    unsigned long long wiE[4], wiO[4], bias[4];
#pragma unroll
    for (int jj = 0; jj < 4; jj++) {
        const int j = jb + jj;
        wiE[jj]  = pk2(w_ih[j * NC + 0], w_ih[j * NC + 1]);
        wiO[jj]  = pk2(w_ih[j * NC + 2], w_ih[j * NC + 3]);
        bias[jj] = pk2(b_ih[j] + b_hh[j], 0.0f);   // counted once by horizontal add
    }

    // seq for this row: 16 B per timestep; all 8 lanes of a row load the same
    // address (L1tex dedups the broadcast). 2-step register prefetch.
    const float4* sp = (const float4*)(seq + (size_t)row * (NT * NC));
    float4 s0 = sp[0];
    float4 s1 = sp[1];

    // register-resident hidden state: pairs (h_jb,h_jb+1), (h_jb+2,h_jb+3)
    unsigned long long hA = 0ULL, hB = 0ULL;

    for (int t = 0; t < NT; t++) {
        const float4 cs = s0;
        s0 = s1;
        const int tn = (t + 2 < NT) ? (t + 2) : (NT - 1);
        s1 = sp[tn];

        const unsigned long long sv = pk2(cs.x, cs.y);
        const unsigned long long sw = pk2(cs.z, cs.w);

        // x_proj seeds (independent of h chain)
        unsigned long long aE0 = fma2(sv, wiE[0], bias[0]);
        unsigned long long aE1 = fma2(sv, wiE[1], bias[1]);
        unsigned long long aE2 = fma2(sv, wiE[2], bias[2]);
        unsigned long long aE3 = fma2(sv, wiE[3], bias[3]);
        unsigned long long aO0 = fma2(sw, wiO[0], 0ULL);
        unsigned long long aO1 = fma2(sw, wiO[1], 0ULL);
        unsigned long long aO2 = fma2(sw, wiO[2], 0ULL);
        unsigned long long aO3 = fma2(sw, wiO[3], 0ULL);

        // recurrence: gather 16 h-pairs of this row via width-8 shuffles.
        // Pair p lives on lane (p>>1) of the row, in hA (p even) / hB (p odd).
#pragma unroll
        for (int p = 0; p < NH / 2; p++) {
            const unsigned long long hp =
                __shfl_sync(0xffffffffu, (p & 1) ? hB : hA, p >> 1, 8);
            if (p & 1) {
                aO0 = fma2(w2[0][p], hp, aO0);
                aO1 = fma2(w2[1][p], hp, aO1);
                aO2 = fma2(w2[2][p], hp, aO2);
                aO3 = fma2(w2[3][p], hp, aO3);
            } else {
                aE0 = fma2(w2[0][p], hp, aE0);
                aE1 = fma2(w2[1][p], hp, aE1);
                aE2 = fma2(w2[2][p], hp, aE2);
                aE3 = fma2(w2[3][p], hp, aE3);
            }
        }

        // horizontal reduce + relu + repack (pure register ops)
        float lo0, hi0, lo1, hi1, lo2, hi2, lo3, hi3;
        upk2(add2(aE0, aO0), lo0, hi0);
        upk2(add2(aE1, aO1), lo1, hi1);
        upk2(add2(aE2, aO2), lo2, hi2);
        upk2(add2(aE3, aO3), lo3, hi3);
        const float v0 = fmaxf(lo0 + hi0, 0.0f);
        const float v1 = fmaxf(lo1 + hi1, 0.0f);
        const float v2 = fmaxf(lo2 + hi2, 0.0f);
        const float v3 = fmaxf(lo3 + hi3, 0.0f);
        hA = pk2(v0, v1);
        hB = pk2(v2, v3);
    }

    // ---- FC head: partials over owned 4 h, then width-8 xor reduction ----
    float hv0, hv1, hv2, hv3;
    upk2(hA, hv0, hv1);
    upk2(hB, hv2, hv3);

    float po[NO];
#pragma unroll
    for (int o = 0; o < NO; o++) {
        const float* fw = fc_w + o * NH + jb;
        po[o] = fmaf(hv0, fw[0],
                fmaf(hv1, fw[1],
                fmaf(hv2, fw[2], hv3 * fw[3])));
    }
#pragma unroll
    for (int off = 4; off >= 1; off >>= 1) {
#pragma unroll
        for (int o = 0; o < NO; o++)
            po[o] += __shfl_xor_sync(0xffffffffu, po[o], off, 8);
    }
    if (q == 0) {
#pragma unroll
        for (int o = 0; o < NO; o++)
            out[row * NO + o] = po[o] + fc_b[o];
    }
}

extern "C" void kernel_launch(void* const* d_in, const int* in_sizes, int n_in,
                              void* d_out, int out_size) {
    const float* seq  = (const float*)d_in[0];
    const float* w_ih = (const float*)d_in[1];
    const float* w_hh = (const float*)d_in[2];
    const float* b_ih = (const float*)d_in[3];
    const float* b_hh = (const float*)d_in[4];
    const float* fc_w = (const float*)d_in[5];
    const float* fc_b = (const float*)d_in[6];
    float* out = (float*)d_out;

    rnn_fused_kernel<<<NBLOCKS, 32>>>(seq, w_ih, w_hh, b_ih, b_hh,
                                      fc_w, fc_b, out);
}